// round 2
// baseline (speedup 1.0000x reference)
#include <cuda_runtime.h>

// GroupAvgPool1d: feature[b,g,c] = sum_{n: y[b,n]==g} x[b,n,c] / N ; mask[b,g] = count>0
// Fixed shapes from the dataset: B=16, N=8192, C=64, G=512.
// NOTE: y is int32 on device (JAX x64 disabled -> astype(int64) is a no-op to int32).
#define BB 16
#define NN 8192
#define CC 64
#define GG 512

#define THREADS 128            // 4 warps per CTA
#define GROUPS_PER_WARP 4
#define GROUPS_PER_CTA 16      // 4 warps * 4 groups
#define CTAS_PER_BATCH 32      // 512 / 16

// Process one 32-row ballot window: yv = this lane's y value for the window,
// base = window start row. Whole warp cooperates on each matched row.
#define PROCESS_WINDOW(bal, yv, base)                                      \
    while (bal) {                                                          \
        int src = __ffs(bal) - 1;                                          \
        bal &= bal - 1;                                                    \
        int info = __shfl_sync(0xffffffffu, (yv), src);                    \
        int row  = (base) + src;                                           \
        float2 v = xb[row * 32 + lane];                                    \
        int which = info & 3;                                              \
        if (which == 0)      { a0.x += v.x; a0.y += v.y; c0++; }           \
        else if (which == 1) { a1.x += v.x; a1.y += v.y; c1++; }           \
        else if (which == 2) { a2.x += v.x; a2.y += v.y; c2++; }           \
        else                 { a3.x += v.x; a3.y += v.y; c3++; }           \
    }

__global__ __launch_bounds__(THREADS)
void group_avg_pool_kernel(const float* __restrict__ x,
                           const int* __restrict__ y,
                           float* __restrict__ out)
{
    __shared__ int sy[NN];   // 32 KB: y[b,:]

    const int b    = blockIdx.y;
    const int gblk = blockIdx.x;          // which block of 16 groups
    const int tid  = threadIdx.x;

    // Stage y[b,:] into shared memory with vectorized int4 loads.
    {
        const int4* y4 = (const int4*)(y + (long long)b * NN);
        int4* sy4 = (int4*)sy;
        #pragma unroll 4
        for (int i = tid; i < NN / 4; i += THREADS) {
            sy4[i] = y4[i];
        }
    }
    __syncthreads();

    const int warp = tid >> 5;
    const int lane = tid & 31;

    // This warp owns groups [gbase, gbase+4). kq = gbase>>2 for the quick match test.
    const int gbase = gblk * GROUPS_PER_CTA + warp * GROUPS_PER_WARP;
    const unsigned kq = (unsigned)(gbase >> 2);

    const float2* xb = (const float2*)(x + (long long)b * NN * CC);

    float2 a0 = {0.f, 0.f}, a1 = {0.f, 0.f}, a2 = {0.f, 0.f}, a3 = {0.f, 0.f};
    int c0 = 0, c1 = 0, c2 = 0, c3 = 0;

    // Scan all rows of this batch; 4 windows per iteration to pipeline the LDS.
    for (int base = 0; base < NN; base += 128) {
        int yv0 = sy[base + lane];
        int yv1 = sy[base + 32 + lane];
        int yv2 = sy[base + 64 + lane];
        int yv3 = sy[base + 96 + lane];
        // unsigned >>2 compare: negative y (dropped rows) can never match kq < 128.
        unsigned b0 = __ballot_sync(0xffffffffu, ((unsigned)yv0 >> 2) == kq);
        unsigned b1 = __ballot_sync(0xffffffffu, ((unsigned)yv1 >> 2) == kq);
        unsigned b2 = __ballot_sync(0xffffffffu, ((unsigned)yv2 >> 2) == kq);
        unsigned b3 = __ballot_sync(0xffffffffu, ((unsigned)yv3 >> 2) == kq);
        PROCESS_WINDOW(b0, yv0, base)
        PROCESS_WINDOW(b1, yv1, base + 32)
        PROCESS_WINDOW(b2, yv2, base + 64)
        PROCESS_WINDOW(b3, yv3, base + 96)
    }

    // Write results. Each (b,g) is owned by exactly one warp -> no races, full coverage.
    const float scale = 1.0f / (float)NN;
    float2* fout = (float2*)out;  // feature[b,g,c]: index (b*GG+g)*32 + lane (float2 units)
    const int fb = (b * GG + gbase) * 32 + lane;
    fout[fb + 0 * 32] = make_float2(a0.x * scale, a0.y * scale);
    fout[fb + 1 * 32] = make_float2(a1.x * scale, a1.y * scale);
    fout[fb + 2 * 32] = make_float2(a2.x * scale, a2.y * scale);
    fout[fb + 3 * 32] = make_float2(a3.x * scale, a3.y * scale);

    if (lane == 0) {
        float* mout = out + (long long)BB * GG * CC;  // mask tail
        const int mb = b * GG + gbase;
        mout[mb + 0] = c0 ? 1.0f : 0.0f;
        mout[mb + 1] = c1 ? 1.0f : 0.0f;
        mout[mb + 2] = c2 ? 1.0f : 0.0f;
        mout[mb + 3] = c3 ? 1.0f : 0.0f;
    }
}

extern "C" void kernel_launch(void* const* d_in, const int* in_sizes, int n_in,
                              void* d_out, int out_size)
{
    const float* x = (const float*)d_in[0];
    const int*   y = (const int*)d_in[1];
    float*     out = (float*)d_out;

    dim3 grid(CTAS_PER_BATCH, BB);   // 32 x 16 = 512 CTAs
    group_avg_pool_kernel<<<grid, THREADS>>>(x, y, out);
}

// round 3
// speedup vs baseline: 1.3939x; 1.3939x over previous
#include <cuda_runtime.h>

// GroupAvgPool1d: feature[b,g,c] = sum_{n: y[b,n]==g} x[b,n,c] / N ; mask[b,g] = count>0
// Shapes: B=16, N=8192, C=64, G=512. y is int32 on device.
#define BB 16
#define NN 8192
#define CC 64
#define GG 512

#define THREADS 128            // 4 warps per CTA
#define GROUPS_PER_WARP 4
#define GROUPS_PER_CTA 16      // 4 warps * 4 groups
#define CTAS_PER_BATCH 32      // 512 / 16
#define NSPLIT 4
#define SLICE (NN / NSPLIT)    // 2048 rows per CTA

#define FEAT_ELEMS (BB * GG * CC)   // 524288 floats

// ---------------------------------------------------------------------------
// Init kernel: zero the feature region; CTAs 0..15 also compute mask[b,:].
// ---------------------------------------------------------------------------
__global__ __launch_bounds__(256)
void init_kernel(const int* __restrict__ y, float* __restrict__ out)
{
    // Zero feature region with float4 stores, grid-stride.
    float4* f4 = (float4*)out;
    const int n4 = FEAT_ELEMS / 4;
    for (int i = blockIdx.x * 256 + threadIdx.x; i < n4; i += gridDim.x * 256)
        f4[i] = make_float4(0.f, 0.f, 0.f, 0.f);

    // Mask: one CTA per batch.
    if (blockIdx.x < BB) {
        const int b = blockIdx.x;
        __shared__ int flag[GG];
        for (int g = threadIdx.x; g < GG; g += 256) flag[g] = 0;
        __syncthreads();
        const int* yb = y + b * NN;
        for (int i = threadIdx.x; i < NN; i += 256) {
            unsigned g = (unsigned)yb[i];
            if (g < GG) flag[g] = 1;
        }
        __syncthreads();
        float* mout = out + FEAT_ELEMS + b * GG;
        for (int g = threadIdx.x; g < GG; g += 256)
            mout[g] = flag[g] ? 1.0f : 0.0f;
    }
}

// ---------------------------------------------------------------------------
// Accumulation kernel: ownership-partitioned gather over an N-slice, then
// global float reductions into the feature output.
// ---------------------------------------------------------------------------
__device__ __forceinline__ void red_add2(float2* p, float x, float yv)
{
    asm volatile("red.global.add.v2.f32 [%0], {%1, %2};"
                 :: "l"(p), "f"(x), "f"(yv) : "memory");
}

#define PROCESS_WINDOW(bal, yv, base)                                      \
    while (bal) {                                                          \
        int src = __ffs(bal) - 1;                                          \
        bal &= bal - 1;                                                    \
        int info = __shfl_sync(0xffffffffu, (yv), src);                    \
        int row  = (base) + src;                                           \
        float2 v = xb[row * 32 + lane];                                    \
        int which = info & 3;                                              \
        if (which == 0)      { a0.x += v.x; a0.y += v.y; }                 \
        else if (which == 1) { a1.x += v.x; a1.y += v.y; }                 \
        else if (which == 2) { a2.x += v.x; a2.y += v.y; }                 \
        else                 { a3.x += v.x; a3.y += v.y; }                 \
    }

__global__ __launch_bounds__(THREADS)
void accum_kernel(const float* __restrict__ x,
                  const int* __restrict__ y,
                  float* __restrict__ out)
{
    __shared__ int sy[SLICE];   // 8 KB: this CTA's y slice

    const int b    = blockIdx.y;
    const int gblk = blockIdx.x;
    const int ns   = blockIdx.z;
    const int tid  = threadIdx.x;
    const int rbase = ns * SLICE;

    // Stage y slice with int4 loads.
    {
        const int4* y4 = (const int4*)(y + b * NN + rbase);
        int4* sy4 = (int4*)sy;
        #pragma unroll 4
        for (int i = tid; i < SLICE / 4; i += THREADS)
            sy4[i] = y4[i];
    }
    __syncthreads();

    const int warp = tid >> 5;
    const int lane = tid & 31;

    const int gbase = gblk * GROUPS_PER_CTA + warp * GROUPS_PER_WARP;
    const unsigned kq = (unsigned)(gbase >> 2);

    // xb points at this slice; rows indexed 0..SLICE-1 within it.
    const float2* xb = (const float2*)(x + ((long long)b * NN + rbase) * CC);

    float2 a0 = {0.f, 0.f}, a1 = {0.f, 0.f}, a2 = {0.f, 0.f}, a3 = {0.f, 0.f};

    for (int base = 0; base < SLICE; base += 128) {
        int yv0 = sy[base + lane];
        int yv1 = sy[base + 32 + lane];
        int yv2 = sy[base + 64 + lane];
        int yv3 = sy[base + 96 + lane];
        unsigned b0 = __ballot_sync(0xffffffffu, ((unsigned)yv0 >> 2) == kq);
        unsigned b1 = __ballot_sync(0xffffffffu, ((unsigned)yv1 >> 2) == kq);
        unsigned b2 = __ballot_sync(0xffffffffu, ((unsigned)yv2 >> 2) == kq);
        unsigned b3 = __ballot_sync(0xffffffffu, ((unsigned)yv3 >> 2) == kq);
        PROCESS_WINDOW(b0, yv0, base)
        PROCESS_WINDOW(b1, yv1, base + 32)
        PROCESS_WINDOW(b2, yv2, base + 64)
        PROCESS_WINDOW(b3, yv3, base + 96)
    }

    // Reduce partials into the output (feature region pre-zeroed by init_kernel).
    const float scale = 1.0f / (float)NN;
    float2* fout = (float2*)out;
    const int fb = (b * GG + gbase) * 32 + lane;
    red_add2(fout + fb + 0 * 32, a0.x * scale, a0.y * scale);
    red_add2(fout + fb + 1 * 32, a1.x * scale, a1.y * scale);
    red_add2(fout + fb + 2 * 32, a2.x * scale, a2.y * scale);
    red_add2(fout + fb + 3 * 32, a3.x * scale, a3.y * scale);
}

extern "C" void kernel_launch(void* const* d_in, const int* in_sizes, int n_in,
                              void* d_out, int out_size)
{
    const float* x = (const float*)d_in[0];
    const int*   y = (const int*)d_in[1];
    float*     out = (float*)d_out;

    init_kernel<<<80, 256>>>(y, out);

    dim3 grid(CTAS_PER_BATCH, BB, NSPLIT);   // 32 x 16 x 4 = 2048 CTAs
    accum_kernel<<<grid, THREADS>>>(x, y, out);
}

// round 5
// speedup vs baseline: 1.5422x; 1.1064x over previous
#include <cuda_runtime.h>

// GroupAvgPool1d: feature[b,g,c] = sum_{n: y[b,n]==g} x[b,n,c] / N ; mask[b,g] = count>0
// Shapes: B=16, N=8192, C=64, G=512. y is int32 on device.
#define BB 16
#define NN 8192
#define CC 64
#define GG 512

#define THREADS 256            // 8 warps per CTA
#define GROUPS_PER_WARP 4
#define GROUPS_PER_CTA 32      // 8 warps * 4 groups
#define CTAS_PER_BATCH 16      // 512 / 32
#define NSPLIT 8
#define SLICE (NN / NSPLIT)    // 1024 rows per CTA

#define FEAT_ELEMS (BB * GG * CC)   // 524288 floats

// ---------------------------------------------------------------------------
// Init kernel: zero the feature region; CTAs 0..15 also compute mask[b,:].
// ---------------------------------------------------------------------------
__global__ __launch_bounds__(256)
void init_kernel(const int* __restrict__ y, float* __restrict__ out)
{
    float4* f4 = (float4*)out;
    const int n4 = FEAT_ELEMS / 4;
    for (int i = blockIdx.x * 256 + threadIdx.x; i < n4; i += gridDim.x * 256)
        f4[i] = make_float4(0.f, 0.f, 0.f, 0.f);

    if (blockIdx.x < BB) {
        const int b = blockIdx.x;
        __shared__ int flag[GG];
        for (int g = threadIdx.x; g < GG; g += 256) flag[g] = 0;
        __syncthreads();
        const int* yb = y + b * NN;
        for (int i = threadIdx.x; i < NN; i += 256) {
            unsigned g = (unsigned)yb[i];
            if (g < GG) flag[g] = 1;
        }
        __syncthreads();
        float* mout = out + FEAT_ELEMS + b * GG;
        for (int g = threadIdx.x; g < GG; g += 256)
            mout[g] = flag[g] ? 1.0f : 0.0f;
    }
}

// ---------------------------------------------------------------------------
// Accumulation kernel: ownership-partitioned gather over an N-slice, then
// global float reductions into the feature output.
// ---------------------------------------------------------------------------
__device__ __forceinline__ void red_add2(float2* p, float x, float yv)
{
    asm volatile("red.global.add.v2.f32 [%0], {%1, %2};"
                 :: "l"(p), "f"(x), "f"(yv) : "memory");
}

#define PROCESS_WINDOW(bal, yv, base)                                      \
    while (bal) {                                                          \
        int src = __ffs(bal) - 1;                                          \
        bal &= bal - 1;                                                    \
        int info = __shfl_sync(0xffffffffu, (yv), src);                    \
        int row  = (base) + src;                                           \
        float2 v = xb[row * 32 + lane];                                    \
        int which = info & 3;                                              \
        if (which == 0)      { a0.x += v.x; a0.y += v.y; }                 \
        else if (which == 1) { a1.x += v.x; a1.y += v.y; }                 \
        else if (which == 2) { a2.x += v.x; a2.y += v.y; }                 \
        else                 { a3.x += v.x; a3.y += v.y; }                 \
    }

__global__ __launch_bounds__(THREADS)
void accum_kernel(const float* __restrict__ x,
                  const int* __restrict__ y,
                  float* __restrict__ out)
{
    __shared__ int sy[SLICE];   // 4 KB: this CTA's y slice

    const int b    = blockIdx.y;
    const int gblk = blockIdx.x;
    const int ns   = blockIdx.z;
    const int tid  = threadIdx.x;
    const int rbase = ns * SLICE;

    // Stage y slice with int4 loads (1 per thread).
    {
        const int4* y4 = (const int4*)(y + b * NN + rbase);
        int4* sy4 = (int4*)sy;
        #pragma unroll
        for (int i = tid; i < SLICE / 4; i += THREADS)
            sy4[i] = y4[i];
    }
    __syncthreads();

    const int warp = tid >> 5;
    const int lane = tid & 31;

    const int gbase = gblk * GROUPS_PER_CTA + warp * GROUPS_PER_WARP;
    const unsigned kq = (unsigned)(gbase >> 2);

    const float2* xb = (const float2*)(x + ((long long)b * NN + rbase) * CC);

    float2 a0 = {0.f, 0.f}, a1 = {0.f, 0.f}, a2 = {0.f, 0.f}, a3 = {0.f, 0.f};

    #pragma unroll
    for (int base = 0; base < SLICE; base += 128) {
        int yv0 = sy[base + lane];
        int yv1 = sy[base + 32 + lane];
        int yv2 = sy[base + 64 + lane];
        int yv3 = sy[base + 96 + lane];
        unsigned b0 = __ballot_sync(0xffffffffu, ((unsigned)yv0 >> 2) == kq);
        unsigned b1 = __ballot_sync(0xffffffffu, ((unsigned)yv1 >> 2) == kq);
        unsigned b2 = __ballot_sync(0xffffffffu, ((unsigned)yv2 >> 2) == kq);
        unsigned b3 = __ballot_sync(0xffffffffu, ((unsigned)yv3 >> 2) == kq);
        PROCESS_WINDOW(b0, yv0, base)
        PROCESS_WINDOW(b1, yv1, base + 32)
        PROCESS_WINDOW(b2, yv2, base + 64)
        PROCESS_WINDOW(b3, yv3, base + 96)
    }

    // Reduce partials into the output (feature region pre-zeroed by init_kernel).
    const float scale = 1.0f / (float)NN;
    float2* fout = (float2*)out;
    const int fb = (b * GG + gbase) * 32 + lane;
    red_add2(fout + fb + 0 * 32, a0.x * scale, a0.y * scale);
    red_add2(fout + fb + 1 * 32, a1.x * scale, a1.y * scale);
    red_add2(fout + fb + 2 * 32, a2.x * scale, a2.y * scale);
    red_add2(fout + fb + 3 * 32, a3.x * scale, a3.y * scale);
}

extern "C" void kernel_launch(void* const* d_in, const int* in_sizes, int n_in,
                              void* d_out, int out_size)
{
    const float* x = (const float*)d_in[0];
    const int*   y = (const int*)d_in[1];
    float*     out = (float*)d_out;

    init_kernel<<<148, 256>>>(y, out);

    dim3 grid(CTAS_PER_BATCH, BB, NSPLIT);   // 16 x 16 x 8 = 2048 CTAs
    accum_kernel<<<grid, THREADS>>>(x, y, out);
}